// round 8
// baseline (speedup 1.0000x reference)
#include <cuda_runtime.h>

// GAE backward scan — warp-per-sequence, segmented-suffix-sum via ballot.
//
// gae_t = d_t + m_t*gae_{t+1},  m_t = GL*(1-term_t), term ∈ {0,1} exactly.
// m is binary -> propagation structure is a termination bitmask (ballot).
// With w_l = d_l*GL^l the within-chunk scan is a plain suffix sum (5
// shuffles/agent); segment edges resolved by one variable-index shuffle:
// gae_l = (S_l - S_{e_l+1}) * GL^{-l} (+ carry if suffix unbroken).
//
// Reads: __ldcs (use-once stream, evict-first keeps L2 for outputs).
// Writes: plain write-back -> dirty output lines (67MB) sit in L2 (126MB)
// and drain outside the hot window instead of competing with the read stream.

#define GAMMA  0.99f
#define LMBDA  0.95f
#define GLF    (GAMMA * LMBDA)

#define B_TOT  8192
#define T_TOT  256
#define NTHREADS 128
#define WARPS_PER_BLOCK (NTHREADS / 32)
#define FULL 0xffffffffu

// one agent's segmented suffix scan for a 32-step chunk
__device__ __forceinline__ float comp_gae(float w, unsigned M, float carry,
                                          int lane, float invglp, float gl32)
{
    // plain suffix sum S_l = sum_{j>=l} w_j
    float S = w;
    #pragma unroll
    for (int off = 1; off < 32; off <<= 1) {
        const float t = __shfl_down_sync(FULL, S, off);
        if (lane + off < 32) S += t;
    }

    // first termination at or after this lane bounds the segment
    const unsigned Mge = M >> lane;
    const int src = Mge ? (lane + __ffs(Mge)) : 32;   // e_l + 1
    const float Sg = __shfl_sync(FULL, S, src);       // clamped if src==32
    float acc = S - (src < 32 ? Sg : 0.0f);
    if (!Mge) acc = fmaf(carry, gl32, acc);           // carry only on unbroken suffix
    return acc * invglp;
}

__global__ __launch_bounds__(NTHREADS, 9)
void gae_kernel(const float4* __restrict__ reward,
                const float4* __restrict__ terminated,
                const float4* __restrict__ value,
                const float4* __restrict__ next_value,
                float4* __restrict__ adv_out,
                float4* __restrict__ ret_out)
{
    const int warp = blockIdx.x * WARPS_PER_BLOCK + (threadIdx.x >> 5);
    const int lane = threadIdx.x & 31;
    const int base = warp * T_TOT + lane;     // float4 element index (< 2^21)

    // per-lane scale constants
    const float glp    = __powf(GLF, (float)lane);   // GL^lane
    const float invglp = 1.0f / glp;                 // GL^-lane
    const float gl32   = __powf(GLF, 32.0f);         // GL^32

    float cx = 0.0f, cy = 0.0f, cz = 0.0f, cw = 0.0f;   // gae carry

    // prefetch chunk 7
    float4 r  = __ldcs(reward     + base + 7 * 32);
    float4 tm = __ldcs(terminated + base + 7 * 32);
    float4 v  = __ldcs(value      + base + 7 * 32);
    float4 nv = __ldcs(next_value + base + 7 * 32);

    #pragma unroll
    for (int c = T_TOT / 32 - 1; c >= 0; --c) {
        const float4 rr = r, tt = tm, vv = v, nn = nv;

        // issue next (earlier) chunk's loads — independent of the scan
        if (c > 0) {
            const int g2 = base + (c - 1) * 32;
            r  = __ldcs(reward     + g2);
            tm = __ldcs(terminated + g2);
            v  = __ldcs(value      + g2);
            nv = __ldcs(next_value + g2);
        }

        // termination masks (one ballot per agent)
        const unsigned Mx = __ballot_sync(FULL, tt.x != 0.0f);
        const unsigned My = __ballot_sync(FULL, tt.y != 0.0f);
        const unsigned Mz = __ballot_sync(FULL, tt.z != 0.0f);
        const unsigned Mw = __ballot_sync(FULL, tt.w != 0.0f);

        // deltas, pre-scaled by GL^lane
        const float ndx = 1.0f - tt.x, ndy = 1.0f - tt.y;
        const float ndz = 1.0f - tt.z, ndw = 1.0f - tt.w;
        const float wx = (rr.x + GAMMA * nn.x * ndx - vv.x) * glp;
        const float wy = (rr.y + GAMMA * nn.y * ndy - vv.y) * glp;
        const float wz = (rr.z + GAMMA * nn.z * ndz - vv.z) * glp;
        const float ww = (rr.w + GAMMA * nn.w * ndw - vv.w) * glp;

        float4 gae;
        gae.x = comp_gae(wx, Mx, cx, lane, invglp, gl32);
        gae.y = comp_gae(wy, My, cy, lane, invglp, gl32);
        gae.z = comp_gae(wz, Mz, cz, lane, invglp, gl32);
        gae.w = comp_gae(ww, Mw, cw, lane, invglp, gl32);

        // write-back stores (let outputs absorb into L2, drain later)
        const int g = base + c * 32;
        adv_out[g] = gae;
        float4 ret;
        ret.x = gae.x + vv.x; ret.y = gae.y + vv.y;
        ret.z = gae.z + vv.z; ret.w = gae.w + vv.w;
        ret_out[g] = ret;

        // carry for the next (earlier) chunk = gae at this chunk's first step
        cx = __shfl_sync(FULL, gae.x, 0);
        cy = __shfl_sync(FULL, gae.y, 0);
        cz = __shfl_sync(FULL, gae.z, 0);
        cw = __shfl_sync(FULL, gae.w, 0);
    }
}

extern "C" void kernel_launch(void* const* d_in, const int* in_sizes, int n_in,
                              void* d_out, int out_size)
{
    const float4* reward     = (const float4*)d_in[0];
    const float4* terminated = (const float4*)d_in[1];
    const float4* value      = (const float4*)d_in[2];
    const float4* next_value = (const float4*)d_in[3];

    const int n_elems = B_TOT * T_TOT * 4;            // floats per tensor
    float4* adv_out = (float4*)d_out;
    float4* ret_out = (float4*)((float*)d_out + n_elems);

    dim3 grid(B_TOT / WARPS_PER_BLOCK);   // 2048 blocks, 4 warps each
    dim3 block(NTHREADS);
    gae_kernel<<<grid, block>>>(reward, terminated, value, next_value,
                                adv_out, ret_out);
}